// round 6
// baseline (speedup 1.0000x reference)
#include <cuda_runtime.h>

#define B_DIM 16
#define C_DIM 256
#define N_DIM 16384
#define K_DIM 8
#define NB 64
#define NT64 (N_DIM / NB)       // 256
#define GR 9                    // blocks per b -> grid 9*16=144
#define NSTAGES 10
#define KAPPA 20.0f

// transposed x tile: xt[n][c], addr = n*284 + c + 4*(c>>5)
#define XT_STRIDE 284
#define XT_OFF   0
#define XT_SIZE  (64 * XT_STRIDE)          // 18176
#define MU_OFF   XT_SIZE                   // 18176
#define MU_SIZE  (C_DIM * K_DIM)           // 2048
#define PART_OFF (MU_OFF + MU_SIZE)        // 20224 ; [16 slices][520]
#define PART_SIZE (16 * 520)               // 8320
#define Z_OFF    (PART_OFF + PART_SIZE)    // 28544 ; z[n][k] 64*8 (+pad)
#define Z_SIZE   520
#define SM_OFF   (Z_OFF + Z_SIZE)          // 29064 ; s_M[256][8]
#define SM_SIZE  2048
#define SM_FLOATS (SM_OFF + SM_SIZE)       // 31112
#define SMEM_BYTES (SM_FLOATS * 4)         // ~124.4 KB

__device__ float g_mu[B_DIM * C_DIM * K_DIM];
__device__ float g_M [B_DIM * C_DIM * K_DIM];
__device__ float g_S [B_DIM * K_DIM];

__device__ __forceinline__ float2 ffma2(float2 a, float2 b, float2 c) {
    float2 d;
    asm("fma.rn.f32x2 %0, %1, %2, %3;"
        : "=l"(reinterpret_cast<unsigned long long&>(d))
        : "l"(reinterpret_cast<unsigned long long&>(a)),
          "l"(reinterpret_cast<unsigned long long&>(b)),
          "l"(reinterpret_cast<unsigned long long&>(c)));
    return d;
}

__device__ __forceinline__ int XT(int n, int c) {
    return n * XT_STRIDE + c + ((c >> 5) << 2);
}

__global__ void init_kernel(const float* __restrict__ mu_in) {
    int idx = blockIdx.x * blockDim.x + threadIdx.x;
    if (idx < B_DIM * C_DIM * K_DIM) {
        g_mu[idx] = mu_in[idx & (C_DIM * K_DIM - 1)];
        g_M[idx]  = 0.0f;
    }
    if (idx < B_DIM * K_DIM) g_S[idx] = 0.0f;
}

__global__ __launch_bounds__(1024, 1)
void em_stage(const float* __restrict__ x, int last, float* __restrict__ z_out) {
    extern __shared__ float sm[];
    float* s_xt   = sm + XT_OFF;
    float* s_mu   = sm + MU_OFF;
    float* s_part = sm + PART_OFF;
    float* s_z    = sm + Z_OFF;
    float* s_M    = sm + SM_OFF;

    const int tid  = threadIdx.x;
    const int warp = tid >> 5, lane = tid & 31;
    const int b    = blockIdx.y;
    const float* xb = x + (size_t)b * C_DIM * N_DIM;

    // loader: warp -> (c-block of 32, n-quarter of 16); lane = c within block
    const int ldc  = ((warp & 7) << 5) | lane;
    const int ldn0 = (warp >> 3) << 4;            // 0,16,32,48
    const float* gld = xb + (size_t)ldc * N_DIM + ldn0;

    // reduce mapping (tid < 512): n = tid>>3, k = tid&7
    const int rn = tid >> 3, rk = tid & 7;

    // p2 mapping: c-pair {cp, cp+128}, n-octet
    const int cp  = tid & 127;
    const int nq8 = (tid >> 7) << 3;              // 0,8,...,56

    // ---- prologue ----
    #pragma unroll
    for (int it = 0; it < 2; ++it) {
        int i = it * 1024 + tid;
        s_mu[i] = g_mu[b * (C_DIM * K_DIM) + i];
        s_M[i]  = 0.0f;
    }

    float2 Ml[4] = {{0.f,0.f},{0.f,0.f},{0.f,0.f},{0.f,0.f}};   // c = cp
    float2 Mh[4] = {{0.f,0.f},{0.f,0.f},{0.f,0.f},{0.f,0.f}};   // c = cp+128
    float Sacc = 0.0f;

    const int t0 = blockIdx.x;
    float4 r0, r1, r2, r3;
    {
        const float* g = gld + (size_t)t0 * NB;
        r0 = *(const float4*)(g + 0);  r1 = *(const float4*)(g + 4);
        r2 = *(const float4*)(g + 8);  r3 = *(const float4*)(g + 12);
    }

    for (int t = t0; t < NT64; t += GR) {
        // ---- STS: regs -> transposed tile (scalar scatter, 1 wf each) ----
        {
            float v[16] = {r0.x,r0.y,r0.z,r0.w, r1.x,r1.y,r1.z,r1.w,
                           r2.x,r2.y,r2.z,r2.w, r3.x,r3.y,r3.z,r3.w};
            #pragma unroll
            for (int j = 0; j < 16; ++j)
                s_xt[XT(ldn0 + j, ldc)] = v[j];
        }
        __syncthreads();

        // ---- phase 1: warps 0..15, c-slice 16, lane handles n=lane & lane+32 ----
        if (warp < 16) {
            float2 A[8] = {{0.f,0.f},{0.f,0.f},{0.f,0.f},{0.f,0.f},
                           {0.f,0.f},{0.f,0.f},{0.f,0.f},{0.f,0.f}};
            const int cbase = warp << 4;
            #pragma unroll
            for (int cq = 0; cq < 4; ++cq) {
                int c = cbase + (cq << 2);
                float4 xa = *(const float4*)(s_xt + XT(lane,      c));
                float4 xc = *(const float4*)(s_xt + XT(lane + 32, c));
                const float* xav = (const float*)&xa;
                const float* xcv = (const float*)&xc;
                #pragma unroll
                for (int cc = 0; cc < 4; ++cc) {
                    float4 m0 = *(const float4*)(s_mu + (c + cc) * 8);
                    float4 m1 = *(const float4*)(s_mu + (c + cc) * 8 + 4);
                    float2 x0 = make_float2(xav[cc], xav[cc]);
                    float2 x1 = make_float2(xcv[cc], xcv[cc]);
                    A[0] = ffma2(x0, make_float2(m0.x, m0.y), A[0]);
                    A[1] = ffma2(x0, make_float2(m0.z, m0.w), A[1]);
                    A[2] = ffma2(x0, make_float2(m1.x, m1.y), A[2]);
                    A[3] = ffma2(x0, make_float2(m1.z, m1.w), A[3]);
                    A[4] = ffma2(x1, make_float2(m0.x, m0.y), A[4]);
                    A[5] = ffma2(x1, make_float2(m0.z, m0.w), A[5]);
                    A[6] = ffma2(x1, make_float2(m1.x, m1.y), A[6]);
                    A[7] = ffma2(x1, make_float2(m1.z, m1.w), A[7]);
                }
            }
            // stage partials, swizzled (sw identical for n and n+32)
            int sw = (lane >> 2) & 7;
            float* pb = s_part + warp * 520 + lane * 8;
            pb[0^sw]=A[0].x; pb[1^sw]=A[0].y; pb[2^sw]=A[1].x; pb[3^sw]=A[1].y;
            pb[4^sw]=A[2].x; pb[5^sw]=A[2].y; pb[6^sw]=A[3].x; pb[7^sw]=A[3].y;
            float* pb2 = pb + 256;           // (lane+32)*8
            pb2[0^sw]=A[4].x; pb2[1^sw]=A[4].y; pb2[2^sw]=A[5].x; pb2[3^sw]=A[5].y;
            pb2[4^sw]=A[6].x; pb2[5^sw]=A[6].y; pb2[6^sw]=A[7].x; pb2[7^sw]=A[7].y;
        }
        __syncthreads();

        // ---- reduce over 16 slices + softmax (tid<512: (n,k)) ----
        if (tid < 512) {
            int col = rn * 8 + (rk ^ ((rn >> 2) & 7));
            float v = 0.f;
            #pragma unroll
            for (int w = 0; w < 16; ++w)
                v += s_part[w * 520 + col];
            v *= KAPPA;
            float mx = v;
            mx = fmaxf(mx, __shfl_xor_sync(~0u, mx, 1));
            mx = fmaxf(mx, __shfl_xor_sync(~0u, mx, 2));
            mx = fmaxf(mx, __shfl_xor_sync(~0u, mx, 4));
            float e = __expf(v - mx);
            float s = e;
            s += __shfl_xor_sync(~0u, s, 1);
            s += __shfl_xor_sync(~0u, s, 2);
            s += __shfl_xor_sync(~0u, s, 4);
            float z = e / s;
            s_z[rn * 8 + rk] = z;
            Sacc += z;
            if (last)
                z_out[((size_t)b * N_DIM + (size_t)t * NB + rn) * 8 + rk] = z;
        }
        __syncthreads();

        // ---- prefetch next tile (consumed at next-iter STS) ----
        if (t + GR < NT64) {
            const float* g = gld + (size_t)(t + GR) * NB;
            r0 = *(const float4*)(g + 0);  r1 = *(const float4*)(g + 4);
            r2 = *(const float4*)(g + 8);  r3 = *(const float4*)(g + 12);
        }

        // ---- phase 2: M += x * z, c-pair per thread, z shared ----
        #pragma unroll
        for (int j = 0; j < 8; ++j) {
            int n = nq8 + j;
            float xlo = s_xt[XT(n, cp)];
            float xhi = s_xt[XT(n, cp + 128)];
            float4 za = *(const float4*)(s_z + n * 8);
            float4 zb = *(const float4*)(s_z + n * 8 + 4);
            float2 xl = make_float2(xlo, xlo);
            float2 xh = make_float2(xhi, xhi);
            Ml[0] = ffma2(xl, make_float2(za.x, za.y), Ml[0]);
            Ml[1] = ffma2(xl, make_float2(za.z, za.w), Ml[1]);
            Ml[2] = ffma2(xl, make_float2(zb.x, zb.y), Ml[2]);
            Ml[3] = ffma2(xl, make_float2(zb.z, zb.w), Ml[3]);
            Mh[0] = ffma2(xh, make_float2(za.x, za.y), Mh[0]);
            Mh[1] = ffma2(xh, make_float2(za.z, za.w), Mh[1]);
            Mh[2] = ffma2(xh, make_float2(zb.x, zb.y), Mh[2]);
            Mh[3] = ffma2(xh, make_float2(zb.z, zb.w), Mh[3]);
        }
        __syncthreads();
    }

    // ---- epilogue: M via smem atomics, then one global flush ----
    {
        float* Mlo = s_M + cp * 8;
        float* Mhi = s_M + (cp + 128) * 8;
        atomicAdd(Mlo + 0, Ml[0].x); atomicAdd(Mlo + 1, Ml[0].y);
        atomicAdd(Mlo + 2, Ml[1].x); atomicAdd(Mlo + 3, Ml[1].y);
        atomicAdd(Mlo + 4, Ml[2].x); atomicAdd(Mlo + 5, Ml[2].y);
        atomicAdd(Mlo + 6, Ml[3].x); atomicAdd(Mlo + 7, Ml[3].y);
        atomicAdd(Mhi + 0, Mh[0].x); atomicAdd(Mhi + 1, Mh[0].y);
        atomicAdd(Mhi + 2, Mh[1].x); atomicAdd(Mhi + 3, Mh[1].y);
        atomicAdd(Mhi + 4, Mh[2].x); atomicAdd(Mhi + 5, Mh[2].y);
        atomicAdd(Mhi + 6, Mh[3].x); atomicAdd(Mhi + 7, Mh[3].y);
    }
    __syncthreads();
    #pragma unroll
    for (int it = 0; it < 2; ++it) {
        int i = it * 1024 + tid;
        atomicAdd(g_M + b * (C_DIM * K_DIM) + i, s_M[i]);
    }
    if (tid < 512) {
        Sacc += __shfl_xor_sync(~0u, Sacc, 8);
        Sacc += __shfl_xor_sync(~0u, Sacc, 16);
        if (lane < 8) atomicAdd(g_S + b * K_DIM + lane, Sacc);
    }
}

__global__ void finalize_kernel(int last, float* __restrict__ mu_out) {
    const int k = blockIdx.x;
    const int b = blockIdx.y;
    const int c = threadIdx.x;
    __shared__ float red[256];

    float S = g_S[b * K_DIM + k];
    float val = g_M[((size_t)b * C_DIM + c) * K_DIM + k] / (1e-6f + S);

    red[c] = val * val;
    __syncthreads();
    for (int s = 128; s > 0; s >>= 1) {
        if (c < s) red[c] += red[c + s];
        __syncthreads();
    }
    float m = val / (1e-6f + sqrtf(red[0]));

    g_mu[((size_t)b * C_DIM + c) * K_DIM + k] = m;
    g_M [((size_t)b * C_DIM + c) * K_DIM + k] = 0.0f;
    if (c == 0) g_S[b * K_DIM + k] = 0.0f;
    if (last) mu_out[((size_t)b * K_DIM + k) * C_DIM + c] = m;
}

__global__ void zdiv_kernel(float* __restrict__ z) {
    int idx = blockIdx.x * blockDim.x + threadIdx.x;
    if (idx < B_DIM * N_DIM * K_DIM) {
        int k = idx & 7;
        int b = idx >> 17;
        z[idx] = z[idx] / (1e-6f + g_S[b * K_DIM + k]);
    }
}

extern "C" void kernel_launch(void* const* d_in, const int* in_sizes, int n_in,
                              void* d_out, int out_size) {
    const float* x     = (const float*)d_in[0];
    const float* mu_in = (const float*)d_in[1];
    float* out    = (float*)d_out;
    float* mu_out = out;
    float* z_out  = out + B_DIM * K_DIM * C_DIM;

    cudaFuncSetAttribute(em_stage, cudaFuncAttributeMaxDynamicSharedMemorySize, SMEM_BYTES);

    init_kernel<<<128, 256>>>(mu_in);
    for (int s = 0; s < NSTAGES; ++s) {
        int last = (s == NSTAGES - 1);
        em_stage<<<dim3(GR, B_DIM), 1024, SMEM_BYTES>>>(x, last, z_out);
        if (last) zdiv_kernel<<<(B_DIM * N_DIM * K_DIM) / 256, 256>>>(z_out);
        finalize_kernel<<<dim3(K_DIM, B_DIM), 256>>>(last, mu_out);
    }
}